// round 12
// baseline (speedup 1.0000x reference)
#include <cuda_runtime.h>
#include <cuda_bf16.h>
#include <cstdint>
#include <math.h>

// ---------------- problem constants ----------------
#define BATCH   32
#define SEQ     1024
#define CH      384          // C == H == 384
#define KTOT    1152         // 3 * 384
#define MAXOUT  3072
#define ROWS    (BATCH*SEQ)  // 32768

// GEMM tiling (R9 proven config)
#define TM      128
#define KC      32
#define NITER   (KTOT/KC)    // 36
#define APAD    40           // halves per A smem row -> 80B stride, LDSM conflict-free
#define BPAD    40
#define NTHR    512
#define NSTAGE  4
#define NTILES  256          // conv tiles per layer
#define TPB     8            // tiles per batch

// smem layout (bytes)
#define A_BYTES (TM*APAD*2)                    // 10240
#define B_BYTES (CH*BPAD*2)                    // 30720
#define OFF_B     (NSTAGE*A_BYTES)             // 40960
#define OFF_PARAM (OFF_B + NSTAGE*B_BYTES)     // 163840
#define OFF_PART  (OFF_PARAM + 4*CH*4)         // 169984
#define OFF_MEAN  (OFF_PART + TM*8*4)          // 174080
#define OFF_RSTD  (OFF_MEAN + TM*4)            // 174592
#define OFF_STAGE (OFF_RSTD + TM*4)            // 175104 : gather staging [2][2][512]x16B
#define SMEM_TOTAL (OFF_STAGE + 32768)         // 207872  (max 232448)

// ---------------- device scratch (no allocations allowed) ----------------
__device__ __nv_bfloat16 g_xbf[ROWS*CH];     // bf16 copy of x
__device__ __nv_bfloat16 g_h1 [ROWS*CH];     // layer-1 output (bf16)
__device__ __nv_bfloat16 g_w1T[CH*KTOT];     // w1 transposed: [o][k*CH+c]
__device__ __nv_bfloat16 g_w2T[CH*KTOT];
__device__ int           g_src[BATCH*MAXOUT]; // absolute x row per res row, or -1
__device__ int           g_flag[NTILES];     // layer-1 tile completion flags

// ---------------- merged prep kernel ----------------
// blocks 0..31: per-batch cumsum + res source-index table
// blocks 32.. : x/w bf16 conversion + flag reset
#define N2     (ROWS*CH/2)
#define WN     (CH*KTOT)
#define CVT_TOTAL (N2 + 2*WN + NTILES)

__global__ void prep_kernel(const float* __restrict__ x,
                            const float* __restrict__ w1,
                            const float* __restrict__ w2,
                            const int*   __restrict__ dur) {
    if (blockIdx.x < BATCH) {
        __shared__ int cum[SEQ];
        __shared__ int part[256];
        const int b = blockIdx.x, t = threadIdx.x;
        int v0 = dur[b*SEQ + t*4], v1 = dur[b*SEQ + t*4+1];
        int v2 = dur[b*SEQ + t*4+2], v3 = dur[b*SEQ + t*4+3];
        part[t] = v0 + v1 + v2 + v3;
        __syncthreads();
        #pragma unroll
        for (int off = 1; off < 256; off <<= 1) {
            int a = (t >= off) ? part[t - off] : 0;
            __syncthreads();
            part[t] += a;
            __syncthreads();
        }
        int run = t ? part[t-1] : 0;
        run += v0; cum[t*4]   = run;
        run += v1; cum[t*4+1] = run;
        run += v2; cum[t*4+2] = run;
        run += v3; cum[t*4+3] = run;
        __syncthreads();
        const int total = cum[SEQ-1];
        for (int t2 = t; t2 < MAXOUT; t2 += 256) {
            int lo = 0, hi = SEQ;
            while (lo < hi) { int mid = (lo+hi)>>1; if (cum[mid] <= t2) lo = mid+1; else hi = mid; }
            g_src[b*MAXOUT + t2] = (t2 < total) ? (b*SEQ + min(lo, SEQ-1)) : -1;
        }
        return;
    }
    int i = (blockIdx.x - BATCH) * blockDim.x + threadIdx.x;
    if (i < N2) {
        float2 v = reinterpret_cast<const float2*>(x)[i];
        reinterpret_cast<__nv_bfloat162*>(g_xbf)[i] = __floats2bfloat162_rn(v.x, v.y);
    } else if (i < N2 + 2*WN) {
        int j = i - N2;
        const float* w = (j < WN) ? w1 : w2;
        __nv_bfloat16* dst = (j < WN) ? g_w1T : g_w2T;
        if (j >= WN) j -= WN;
        int o  = j / KTOT;
        int kc = j - o * KTOT;
        dst[(size_t)o * KTOT + kc] = __float2bfloat16(w[(size_t)kc * CH + o]);
    } else if (i < CVT_TOTAL) {
        g_flag[i - N2 - 2*WN] = 0;
    }
}

// ---------------- ptx helpers ----------------
__device__ __forceinline__ void mma16816(float* c, const uint32_t* a, uint32_t b0, uint32_t b1) {
    asm volatile(
        "mma.sync.aligned.m16n8k16.row.col.f32.bf16.bf16.f32 "
        "{%0,%1,%2,%3}, {%4,%5,%6,%7}, {%8,%9}, {%0,%1,%2,%3};\n"
        : "+f"(c[0]), "+f"(c[1]), "+f"(c[2]), "+f"(c[3])
        : "r"(a[0]), "r"(a[1]), "r"(a[2]), "r"(a[3]), "r"(b0), "r"(b1));
}
__device__ __forceinline__ void ldsm4(uint32_t* r, uint32_t addr) {
    asm volatile("ldmatrix.sync.aligned.m8n8.x4.shared.b16 {%0,%1,%2,%3}, [%4];\n"
                 : "=r"(r[0]), "=r"(r[1]), "=r"(r[2]), "=r"(r[3]) : "r"(addr));
}
__device__ __forceinline__ void cp_async16(uint32_t dst, const void* gptr, int sz) {
    asm volatile("cp.async.cg.shared.global [%0], [%1], 16, %2;\n" :: "r"(dst), "l"(gptr), "r"(sz));
}
__device__ __forceinline__ void cp_async16(uint32_t dst, const void* gptr) {
    asm volatile("cp.async.cg.shared.global [%0], [%1], 16;\n" :: "r"(dst), "l"(gptr));
}
__device__ __forceinline__ void cp_commit() { asm volatile("cp.async.commit_group;\n"); }
__device__ __forceinline__ void cp_wait1()  { asm volatile("cp.async.wait_group 1;\n"); }
__device__ __forceinline__ void cp_wait0()  { asm volatile("cp.async.wait_group 0;\n"); }

// ---------------- merged dual-layer conv kernel + embedded gather ----------------
// Blocks 0..255:   layer 1 tiles -> g_h1 + flag; ALSO stream 384 res rows (gather)
// Blocks 256..511: layer 2 tiles (spin on <=3 neighbor flags) -> pred
__global__ __launch_bounds__(NTHR, 1)
void conv_ln_kernel(const float* __restrict__ b1v,
                    const float* __restrict__ g1v,
                    const float* __restrict__ be1v,
                    const float* __restrict__ b2v,
                    const float* __restrict__ g2v,
                    const float* __restrict__ be2v,
                    const float* __restrict__ wl,
                    const float* __restrict__ bl,
                    const float* __restrict__ x,
                    float* __restrict__ res,
                    float* __restrict__ pred)
{
    extern __shared__ char smem[];
    const uint32_t smem_base = (uint32_t)__cvta_generic_to_shared(smem);
    float* sBias  = (float*)(smem + OFF_PARAM);
    float* sGamma = sBias  + CH;
    float* sBeta  = sGamma + CH;
    float* sWl    = sBeta  + CH;
    float* sPart  = (float*)(smem + OFF_PART);   // [TM][8]
    float* sMean  = (float*)(smem + OFF_MEAN);   // [TM]
    float* sRstd  = (float*)(smem + OFF_RSTD);   // [TM]

    const bool PRED = blockIdx.x >= NTILES;
    const int  bidx = PRED ? (blockIdx.x - NTILES) : blockIdx.x;   // tile 0..255

    const __nv_bfloat16* Ain = PRED ? g_h1  : g_xbf;
    const __nv_bfloat16* WT  = PRED ? g_w2T : g_w1T;
    const float* bias  = PRED ? b2v  : b1v;
    const float* gamma = PRED ? g2v  : g1v;
    const float* beta  = PRED ? be2v : be1v;

    const int tid  = threadIdx.x;
    const int b    = bidx >> 3;
    const int s0   = (bidx & (TPB - 1)) * TM;
    const size_t rowBase = (size_t)b * SEQ;

    if (tid < CH) {
        sBias[tid]  = bias[tid];
        sGamma[tid] = gamma[tid];
        sBeta[tid]  = beta[tid];
        sWl[tid]    = PRED ? wl[tid] : 0.0f;
    }

    // ---- gather state (L1 CTAs): quad t handles res rows row0..row0+2 ----
    const int quad = tid >> 2, q = tid & 3;
    const int row0 = bidx * 384 + quad * 3;      // flat res row (b*3072 + ...)
    int sA = 0, sB = 0, sC = 0;
    if (!PRED) {
        sA = g_src[row0]; sB = g_src[row0 + 1]; sC = g_src[row0 + 2];
    }
    const float4* xf4   = (const float4*)x;
    float4*       resf4 = (float4*)res;

    // issue one gather batch (2 x 16B per thread) into staging slot ci&1
    auto issue_batch = [&](int ci) {
        #pragma unroll
        for (int e = 0; e < 2; e++) {
            int f  = q + 8 * ci + 4 * e;                       // 0..287
            int ro = (f >= 96) + (f >= 192);
            int seg = f - 96 * ro;
            int srow = (ro == 0) ? sA : ((ro == 1) ? sB : sC);
            uint32_t dst = smem_base + OFF_STAGE + (((ci & 1) * 2 + e) * NTHR + tid) * 16;
            const void* src = (srow >= 0) ? (const void*)(xf4 + (size_t)srow * 96 + seg)
                                          : (const void*)xf4;
            cp_async16(dst, src, (srow >= 0) ? 16 : 0);
        }
    };
    // consume gather batch cb from staging -> res (zeros if invalid)
    auto consume_batch = [&](int cb) {
        #pragma unroll
        for (int e = 0; e < 2; e++) {
            int f  = q + 8 * cb + 4 * e;
            int ro = (f >= 96) + (f >= 192);
            int seg = f - 96 * ro;
            int srow = (ro == 0) ? sA : ((ro == 1) ? sB : sC);
            float4 v = *(const float4*)(smem + OFF_STAGE + (((cb & 1) * 2 + e) * NTHR + tid) * 16);
            if (srow < 0) v = make_float4(0.f, 0.f, 0.f, 0.f);
            resf4[(size_t)(row0 + ro) * 96 + seg] = v;
        }
    };

    // ---- layer-2 blocks: wait for the layer-1 tiles whose rows we read ----
    if (PRED) {
        if (tid == 0) {
            int i = bidx & (TPB - 1), base = bidx & ~(TPB - 1);
            int lo = base + max(i - 1, 0), hi = base + min(i + 1, TPB - 1);
            for (int d = lo; d <= hi; d++)
                while (*(volatile int*)&g_flag[d] == 0) {}
        }
        __threadfence();
        __syncthreads();
    }

    // ---- tile loader (cp.async, padded layout) ----
    auto load_tile = [&](int ci, int st) {
        const int k  = ci / 12;
        const int c0 = (ci % 12) * KC;
        const uint32_t Ad = smem_base + st * A_BYTES;
        const uint32_t Bd = smem_base + OFF_B + st * B_BYTES;
        {   // A: 128 rows x 64B = 512 x 16B reqs
            int r = tid >> 2, seg = tid & 3;
            int gs = s0 + r + k - 1;
            bool ok = (unsigned)gs < (unsigned)SEQ;
            const void* src = ok ? (const void*)(Ain + (rowBase + gs) * CH + c0 + seg * 8)
                                 : (const void*)Ain;
            cp_async16(Ad + (r * APAD + seg * 8) * 2, src, ok ? 16 : 0);
        }
        #pragma unroll
        for (int e = 0; e < 3; e++) {       // B: 384 rows x 64B = 1536 reqs
            int j = tid + e * NTHR;
            int n = j >> 2, seg = j & 3;
            cp_async16(Bd + (n * BPAD + seg * 8) * 2,
                       WT + (size_t)n * KTOT + ci * KC + seg * 8);
        }
    };

    const int wid = tid >> 5, lane = tid & 31;
    const int wm = wid >> 2, wn = wid & 3;   // 4x4 warp grid; warp tile 32(M) x 96(N)

    const int aRow = wm * 32 + (lane & 7) + ((lane >> 3) & 1) * 8;
    const int aCol = (lane >> 4) * 8;
    const uint32_t aBase = (uint32_t)((aRow * APAD + aCol) * 2);
    const int bRow = wn * 96 + (lane & 7) + ((lane >> 4) & 1) * 8;
    const int bCol = ((lane >> 3) & 1) * 8;
    const uint32_t bBase = (uint32_t)((bRow * BPAD + bCol) * 2);

    float c[2][12][4];
    #pragma unroll
    for (int mt = 0; mt < 2; mt++)
        #pragma unroll
        for (int nt = 0; nt < 12; nt++)
            #pragma unroll
            for (int i = 0; i < 4; i++) c[mt][nt][i] = 0.0f;

    load_tile(0, 0); cp_commit();
    load_tile(1, 1); cp_commit();

    for (int ci = 0; ci < NITER; ci++) {
        const int st = ci & 3;
        cp_wait1();                 // group(ci-2) done: tile ci (+ batch ci-2) ready
        __syncthreads();

        if (!PRED) {
            if (ci >= 2) consume_batch(ci - 2);   // read slot, then refill same slot
            issue_batch(ci);
        }
        if (ci + 2 < NITER) load_tile(ci + 2, (ci + 2) & 3);
        cp_commit();

        const uint32_t Asb = smem_base + st * A_BYTES + aBase;
        const uint32_t Bsb = smem_base + OFF_B + st * B_BYTES + bBase;
        #pragma unroll
        for (int ks = 0; ks < 2; ks++) {
            uint32_t a[2][4];
            ldsm4(a[0], Asb + ks * 32);
            ldsm4(a[1], Asb + 16 * APAD * 2 + ks * 32);
            #pragma unroll
            for (int np = 0; np < 6; np++) {
                uint32_t bb[4];
                ldsm4(bb, Bsb + np * 16 * BPAD * 2 + ks * 32);
                mma16816(c[0][2*np  ], a[0], bb[0], bb[1]);
                mma16816(c[1][2*np  ], a[1], bb[0], bb[1]);
                mma16816(c[0][2*np+1], a[0], bb[2], bb[3]);
                mma16816(c[1][2*np+1], a[1], bb[2], bb[3]);
            }
        }
    }
    cp_wait0();
    if (!PRED) {                     // drain last two gather batches
        consume_batch(NITER - 2);
        consume_batch(NITER - 1);
    }
    __syncthreads();

    // ---- epilogue: +bias, LayerNorm stats ----
    const int g = lane >> 2, tg = lane & 3;
    float psum[2][2] = {{0,0},{0,0}}, psq[2][2] = {{0,0},{0,0}};
    #pragma unroll
    for (int mt = 0; mt < 2; mt++)
        #pragma unroll
        for (int nt = 0; nt < 12; nt++) {
            int col0 = wn * 96 + nt * 8 + tg * 2;
            float bb0 = sBias[col0], bb1 = sBias[col0 + 1];
            c[mt][nt][0] += bb0; c[mt][nt][1] += bb1;
            c[mt][nt][2] += bb0; c[mt][nt][3] += bb1;
            psum[mt][0] += c[mt][nt][0] + c[mt][nt][1];
            psq [mt][0] += c[mt][nt][0]*c[mt][nt][0] + c[mt][nt][1]*c[mt][nt][1];
            psum[mt][1] += c[mt][nt][2] + c[mt][nt][3];
            psq [mt][1] += c[mt][nt][2]*c[mt][nt][2] + c[mt][nt][3]*c[mt][nt][3];
        }
    #pragma unroll
    for (int mt = 0; mt < 2; mt++)
        #pragma unroll
        for (int hi = 0; hi < 2; hi++) {
            float s = psum[mt][hi], q2 = psq[mt][hi];
            s  += __shfl_xor_sync(0xffffffffu, s, 1);  s  += __shfl_xor_sync(0xffffffffu, s, 2);
            q2 += __shfl_xor_sync(0xffffffffu, q2, 1); q2 += __shfl_xor_sync(0xffffffffu, q2, 2);
            if (tg == 0) {
                int r = wm * 32 + mt * 16 + g + 8 * hi;
                sPart[r * 8 + wn] = s;
                sPart[r * 8 + 4 + wn] = q2;
            }
        }
    __syncthreads();
    if (tid < TM) {
        float s  = sPart[tid*8+0] + sPart[tid*8+1] + sPart[tid*8+2] + sPart[tid*8+3];
        float q2 = sPart[tid*8+4] + sPart[tid*8+5] + sPart[tid*8+6] + sPart[tid*8+7];
        float mean = s * (1.0f / CH);
        float var  = q2 * (1.0f / CH) - mean * mean;
        sMean[tid] = mean;
        sRstd[tid] = rsqrtf(var + 1e-5f);
    }
    __syncthreads();

    // ---- normalize + relu; store bf16 OR fused linear+exp ----
    float pd[2][2] = {{0,0},{0,0}};
    #pragma unroll
    for (int mt = 0; mt < 2; mt++) {
        int r0 = wm * 32 + mt * 16 + g;
        float m0 = sMean[r0],   rs0 = sRstd[r0];
        float m1 = sMean[r0+8], rs1 = sRstd[r0+8];
        #pragma unroll
        for (int nt = 0; nt < 12; nt++) {
            int col0 = wn * 96 + nt * 8 + tg * 2;
            float ga0 = sGamma[col0], ga1 = sGamma[col0+1];
            float be0 = sBeta[col0],  be1 = sBeta[col0+1];
            float v0 = fmaxf(0.f, (c[mt][nt][0] - m0) * rs0 * ga0 + be0);
            float v1 = fmaxf(0.f, (c[mt][nt][1] - m0) * rs0 * ga1 + be1);
            float v2 = fmaxf(0.f, (c[mt][nt][2] - m1) * rs1 * ga0 + be0);
            float v3 = fmaxf(0.f, (c[mt][nt][3] - m1) * rs1 * ga1 + be1);
            if (!PRED) {
                size_t base0 = (rowBase + s0 + r0) * CH + col0;
                *(__nv_bfloat162*)(g_h1 + base0)          = __floats2bfloat162_rn(v0, v1);
                *(__nv_bfloat162*)(g_h1 + base0 + 8 * CH) = __floats2bfloat162_rn(v2, v3);
            } else {
                float w0 = sWl[col0], w1v = sWl[col0 + 1];
                pd[mt][0] += v0 * w0 + v1 * w1v;
                pd[mt][1] += v2 * w0 + v3 * w1v;
            }
        }
    }
    if (!PRED) {
        __syncthreads();
        __threadfence();
        if (tid == 0) *(volatile int*)&g_flag[bidx] = 1;
    } else {
        #pragma unroll
        for (int mt = 0; mt < 2; mt++)
            #pragma unroll
            for (int hi = 0; hi < 2; hi++) {
                float s = pd[mt][hi];
                s += __shfl_xor_sync(0xffffffffu, s, 1);
                s += __shfl_xor_sync(0xffffffffu, s, 2);
                if (tg == 0) {
                    int r = wm * 32 + mt * 16 + g + 8 * hi;
                    sPart[r * 8 + wn] = s;
                }
            }
        __syncthreads();
        if (tid < TM) {
            float s = sPart[tid*8+0] + sPart[tid*8+1] + sPart[tid*8+2] + sPart[tid*8+3];
            pred[rowBase + s0 + tid] = expf(s + bl[0]);
        }
    }
}

// ---------------- launch ----------------
extern "C" void kernel_launch(void* const* d_in, const int* in_sizes, int n_in,
                              void* d_out, int out_size) {
    const float* x     = (const float*)d_in[0];
    const int*   dur   = (const int*)  d_in[1];
    const float* w1    = (const float*)d_in[2];
    const float* b1    = (const float*)d_in[3];
    const float* g1    = (const float*)d_in[4];
    const float* beta1 = (const float*)d_in[5];
    const float* w2    = (const float*)d_in[6];
    const float* b2    = (const float*)d_in[7];
    const float* g2    = (const float*)d_in[8];
    const float* beta2 = (const float*)d_in[9];
    const float* wl    = (const float*)d_in[10];
    const float* bl    = (const float*)d_in[11];

    float* res  = (float*)d_out;
    float* pred = res + (size_t)BATCH * MAXOUT * CH;

    cudaFuncSetAttribute(conv_ln_kernel, cudaFuncAttributeMaxDynamicSharedMemorySize, SMEM_TOTAL);

    // prep: src table (cumsum+searchsorted) + bf16 conversions + flag reset
    prep_kernel<<<BATCH + (CVT_TOTAL + 255) / 256, 256>>>(x, w1, w2, dur);

    // dual-layer pipelined conv with embedded res gather
    conv_ln_kernel<<<2 * NTILES, NTHR, SMEM_TOTAL>>>(b1, g1, beta1, b2, g2, beta2,
                                                     wl, bl, x, res, pred);
}

// round 13
// speedup vs baseline: 1.2227x; 1.2227x over previous
#include <cuda_runtime.h>
#include <cuda_bf16.h>
#include <cstdint>
#include <math.h>

// ---------------- problem constants ----------------
#define BATCH   32
#define SEQ     1024
#define CH      384          // C == H == 384
#define KTOT    1152         // 3 * 384
#define MAXOUT  3072
#define ROWS    (BATCH*SEQ)  // 32768

// GEMM tiling (R9 proven config)
#define TM      128
#define KC      32
#define NITER   (KTOT/KC)    // 36
#define APAD    40           // halves per A smem row -> 80B stride, LDSM conflict-free
#define BPAD    40
#define NTHR    512
#define NSTAGE  4
#define NTILES  256          // conv tiles per layer
#define TPB     8            // tiles per batch
#define GBLK    148          // tail gather blocks

// smem layout (bytes)
#define A_BYTES (TM*APAD*2)                    // 10240
#define B_BYTES (CH*BPAD*2)                    // 30720
#define OFF_B     (NSTAGE*A_BYTES)             // 40960
#define OFF_PARAM (OFF_B + NSTAGE*B_BYTES)     // 163840
#define OFF_PART  (OFF_PARAM + 4*CH*4)         // 169984
#define OFF_MEAN  (OFF_PART + TM*8*4)          // 174080
#define OFF_RSTD  (OFF_MEAN + TM*4)            // 174592
#define SMEM_TOTAL (OFF_RSTD + TM*4)           // 175104

// ---------------- device scratch (no allocations allowed) ----------------
__device__ __nv_bfloat16 g_xbf[ROWS*CH];     // bf16 copy of x
__device__ __nv_bfloat16 g_h1 [ROWS*CH];     // layer-1 output (bf16)
__device__ __nv_bfloat16 g_w1T[CH*KTOT];     // w1 transposed: [o][k*CH+c]
__device__ __nv_bfloat16 g_w2T[CH*KTOT];
__device__ int           g_src[BATCH*MAXOUT]; // absolute x row per res row, or -1
__device__ int           g_flag[NTILES];     // layer-1 tile completion flags

// ---------------- merged prep kernel ----------------
// blocks 0..31: per-batch cumsum + res source-index table
// blocks 32.. : x/w bf16 conversion + flag reset
#define N2     (ROWS*CH/2)
#define WN     (CH*KTOT)
#define CVT_TOTAL (N2 + 2*WN + NTILES)

__global__ void prep_kernel(const float* __restrict__ x,
                            const float* __restrict__ w1,
                            const float* __restrict__ w2,
                            const int*   __restrict__ dur) {
    if (blockIdx.x < BATCH) {
        __shared__ int cum[SEQ];
        __shared__ int part[256];
        const int b = blockIdx.x, t = threadIdx.x;
        int v0 = dur[b*SEQ + t*4], v1 = dur[b*SEQ + t*4+1];
        int v2 = dur[b*SEQ + t*4+2], v3 = dur[b*SEQ + t*4+3];
        part[t] = v0 + v1 + v2 + v3;
        __syncthreads();
        #pragma unroll
        for (int off = 1; off < 256; off <<= 1) {
            int a = (t >= off) ? part[t - off] : 0;
            __syncthreads();
            part[t] += a;
            __syncthreads();
        }
        int run = t ? part[t-1] : 0;
        run += v0; cum[t*4]   = run;
        run += v1; cum[t*4+1] = run;
        run += v2; cum[t*4+2] = run;
        run += v3; cum[t*4+3] = run;
        __syncthreads();
        const int total = cum[SEQ-1];
        for (int t2 = t; t2 < MAXOUT; t2 += 256) {
            int lo = 0, hi = SEQ;
            while (lo < hi) { int mid = (lo+hi)>>1; if (cum[mid] <= t2) lo = mid+1; else hi = mid; }
            g_src[b*MAXOUT + t2] = (t2 < total) ? (b*SEQ + min(lo, SEQ-1)) : -1;
        }
        return;
    }
    int i = (blockIdx.x - BATCH) * blockDim.x + threadIdx.x;
    if (i < N2) {
        float2 v = reinterpret_cast<const float2*>(x)[i];
        reinterpret_cast<__nv_bfloat162*>(g_xbf)[i] = __floats2bfloat162_rn(v.x, v.y);
    } else if (i < N2 + 2*WN) {
        int j = i - N2;
        const float* w = (j < WN) ? w1 : w2;
        __nv_bfloat16* dst = (j < WN) ? g_w1T : g_w2T;
        if (j >= WN) j -= WN;
        int o  = j / KTOT;
        int kc = j - o * KTOT;
        dst[(size_t)o * KTOT + kc] = __float2bfloat16(w[(size_t)kc * CH + o]);
    } else if (i < CVT_TOTAL) {
        g_flag[i - N2 - 2*WN] = 0;
    }
}

// ---------------- ptx helpers ----------------
__device__ __forceinline__ void mma16816(float* c, const uint32_t* a, uint32_t b0, uint32_t b1) {
    asm volatile(
        "mma.sync.aligned.m16n8k16.row.col.f32.bf16.bf16.f32 "
        "{%0,%1,%2,%3}, {%4,%5,%6,%7}, {%8,%9}, {%0,%1,%2,%3};\n"
        : "+f"(c[0]), "+f"(c[1]), "+f"(c[2]), "+f"(c[3])
        : "r"(a[0]), "r"(a[1]), "r"(a[2]), "r"(a[3]), "r"(b0), "r"(b1));
}
__device__ __forceinline__ void ldsm4(uint32_t* r, uint32_t addr) {
    asm volatile("ldmatrix.sync.aligned.m8n8.x4.shared.b16 {%0,%1,%2,%3}, [%4];\n"
                 : "=r"(r[0]), "=r"(r[1]), "=r"(r[2]), "=r"(r[3]) : "r"(addr));
}
__device__ __forceinline__ void cp_async16(uint32_t dst, const void* gptr, int sz) {
    asm volatile("cp.async.cg.shared.global [%0], [%1], 16, %2;\n" :: "r"(dst), "l"(gptr), "r"(sz));
}
__device__ __forceinline__ void cp_async16(uint32_t dst, const void* gptr) {
    asm volatile("cp.async.cg.shared.global [%0], [%1], 16;\n" :: "r"(dst), "l"(gptr));
}
__device__ __forceinline__ void cp_commit() { asm volatile("cp.async.commit_group;\n"); }
__device__ __forceinline__ void cp_wait2()  { asm volatile("cp.async.wait_group 2;\n"); }
__device__ __forceinline__ void cp_wait1()  { asm volatile("cp.async.wait_group 1;\n"); }
__device__ __forceinline__ void cp_wait0()  { asm volatile("cp.async.wait_group 0;\n"); }

// ---------------- fused kernel ----------------
// Blocks 0..255:    layer 1 conv tiles -> g_h1 + completion flag
// Blocks 256..511:  layer 2 conv tiles (spin on <=3 neighbor flags) -> pred
// Blocks 512..659:  res gather (dispatched last -> fill the conv tail wave)
__global__ __launch_bounds__(NTHR, 1)
void conv_ln_kernel(const float* __restrict__ b1v,
                    const float* __restrict__ g1v,
                    const float* __restrict__ be1v,
                    const float* __restrict__ b2v,
                    const float* __restrict__ g2v,
                    const float* __restrict__ be2v,
                    const float* __restrict__ wl,
                    const float* __restrict__ bl,
                    const float* __restrict__ x,
                    float* __restrict__ res,
                    float* __restrict__ pred)
{
    const int tid = threadIdx.x;

    // ---- tail gather blocks: warp-per-row copy via g_src ----
    if (blockIdx.x >= 2 * NTILES) {
        const int gb = blockIdx.x - 2 * NTILES;       // 0..GBLK-1
        const int wrp = tid >> 5, lane = tid & 31;    // 16 warps per block
        const float4* xf4   = (const float4*)x;
        float4*       resf4 = (float4*)res;
        const float4  z = make_float4(0.f, 0.f, 0.f, 0.f);
        for (int row = gb * 16 + wrp; row < BATCH * MAXOUT; row += GBLK * 16) {
            int srow = g_src[row];
            float4* op = resf4 + (size_t)row * 96;
            if (srow < 0) {
                op[lane] = z; op[lane + 32] = z; op[lane + 64] = z;
            } else {
                const float4* xp = xf4 + (size_t)srow * 96;
                op[lane]      = xp[lane];
                op[lane + 32] = xp[lane + 32];
                op[lane + 64] = xp[lane + 64];
            }
        }
        return;
    }

    extern __shared__ char smem[];
    const uint32_t smem_base = (uint32_t)__cvta_generic_to_shared(smem);
    float* sBias  = (float*)(smem + OFF_PARAM);
    float* sGamma = sBias  + CH;
    float* sBeta  = sGamma + CH;
    float* sWl    = sBeta  + CH;
    float* sPart  = (float*)(smem + OFF_PART);   // [TM][8]
    float* sMean  = (float*)(smem + OFF_MEAN);   // [TM]
    float* sRstd  = (float*)(smem + OFF_RSTD);   // [TM]

    const bool PRED = blockIdx.x >= NTILES;
    const int  bidx = PRED ? (blockIdx.x - NTILES) : blockIdx.x;   // tile 0..255

    const __nv_bfloat16* Ain = PRED ? g_h1  : g_xbf;
    const __nv_bfloat16* WT  = PRED ? g_w2T : g_w1T;
    const float* bias  = PRED ? b2v  : b1v;
    const float* gamma = PRED ? g2v  : g1v;
    const float* beta  = PRED ? be2v : be1v;

    const int b    = bidx >> 3;             // 8 tiles per batch (1024/128)
    const int s0   = (bidx & (TPB - 1)) * TM;
    const size_t rowBase = (size_t)b * SEQ;

    if (tid < CH) {
        sBias[tid]  = bias[tid];
        sGamma[tid] = gamma[tid];
        sBeta[tid]  = beta[tid];
        sWl[tid]    = PRED ? wl[tid] : 0.0f;
    }

    // ---- layer-2 blocks: wait for the layer-1 tiles whose rows we read ----
    if (PRED) {
        if (tid == 0) {
            int i = bidx & (TPB - 1), base = bidx & ~(TPB - 1);
            int lo = base + max(i - 1, 0), hi = base + min(i + 1, TPB - 1);
            for (int d = lo; d <= hi; d++)
                while (*(volatile int*)&g_flag[d] == 0) {}
        }
        __threadfence();
        __syncthreads();
    }

    // ---- tile loader (cp.async, padded layout) ----
    auto load_tile = [&](int ci, int st) {
        const int k  = ci / 12;             // conv tap 0..2
        const int c0 = (ci % 12) * KC;      // channel base within tap
        const uint32_t Ad = smem_base + st * A_BYTES;
        const uint32_t Bd = smem_base + OFF_B + st * B_BYTES;
        {   // A: 128 rows x 64B = 512 x 16B reqs, 1 per thread
            int r = tid >> 2, seg = tid & 3;
            int gs = s0 + r + k - 1;                // batch-local padded row
            bool ok = (unsigned)gs < (unsigned)SEQ;
            const void* src = ok ? (const void*)(Ain + (rowBase + gs) * CH + c0 + seg * 8)
                                 : (const void*)Ain;
            cp_async16(Ad + (r * APAD + seg * 8) * 2, src, ok ? 16 : 0);
        }
        // B: 384 rows x 64B = 1536 reqs, 3 per thread
        #pragma unroll
        for (int e = 0; e < 3; e++) {
            int j = tid + e * NTHR;
            int n = j >> 2, seg = j & 3;
            cp_async16(Bd + (n * BPAD + seg * 8) * 2,
                       WT + (size_t)n * KTOT + ci * KC + seg * 8);
        }
    };

    const int wid = tid >> 5, lane = tid & 31;
    const int wm = wid >> 2, wn = wid & 3;   // 4x4 warp grid; warp tile 32(M) x 96(N)

    const int aRow = wm * 32 + (lane & 7) + ((lane >> 3) & 1) * 8;
    const int aCol = (lane >> 4) * 8;                    // halves
    const uint32_t aBase = (uint32_t)((aRow * APAD + aCol) * 2);
    const int bRow = wn * 96 + (lane & 7) + ((lane >> 4) & 1) * 8;
    const int bCol = ((lane >> 3) & 1) * 8;              // halves
    const uint32_t bBase = (uint32_t)((bRow * BPAD + bCol) * 2);

    float c[2][12][4];
    #pragma unroll
    for (int mt = 0; mt < 2; mt++)
        #pragma unroll
        for (int nt = 0; nt < 12; nt++)
            #pragma unroll
            for (int i = 0; i < 4; i++) c[mt][nt][i] = 0.0f;

    load_tile(0, 0); cp_commit();
    load_tile(1, 1); cp_commit();

    for (int ci = 0; ci < NITER; ci++) {
        const int st = ci & 3;
        if (ci + 2 < NITER) { load_tile(ci + 2, (ci + 2) & 3); cp_commit(); cp_wait2(); }
        else if (ci == NITER - 2) cp_wait1();
        else cp_wait0();
        __syncthreads();

        const uint32_t Asb = smem_base + st * A_BYTES + aBase;
        const uint32_t Bsb = smem_base + OFF_B + st * B_BYTES + bBase;
        #pragma unroll
        for (int ks = 0; ks < 2; ks++) {
            uint32_t a[2][4];
            ldsm4(a[0], Asb + ks * 32);                       // rows wm*32 +  0..15
            ldsm4(a[1], Asb + 16 * APAD * 2 + ks * 32);       // rows wm*32 + 16..31
            #pragma unroll
            for (int np = 0; np < 6; np++) {
                uint32_t bb[4];                               // 2 n8 fragments
                ldsm4(bb, Bsb + np * 16 * BPAD * 2 + ks * 32);
                mma16816(c[0][2*np  ], a[0], bb[0], bb[1]);
                mma16816(c[1][2*np  ], a[1], bb[0], bb[1]);
                mma16816(c[0][2*np+1], a[0], bb[2], bb[3]);
                mma16816(c[1][2*np+1], a[1], bb[2], bb[3]);
            }
        }
    }
    __syncthreads();

    // ---- epilogue: +bias, LayerNorm stats ----
    const int g = lane >> 2, tg = lane & 3;
    float psum[2][2] = {{0,0},{0,0}}, psq[2][2] = {{0,0},{0,0}};
    #pragma unroll
    for (int mt = 0; mt < 2; mt++)
        #pragma unroll
        for (int nt = 0; nt < 12; nt++) {
            int col0 = wn * 96 + nt * 8 + tg * 2;
            float bb0 = sBias[col0], bb1 = sBias[col0 + 1];
            c[mt][nt][0] += bb0; c[mt][nt][1] += bb1;
            c[mt][nt][2] += bb0; c[mt][nt][3] += bb1;
            psum[mt][0] += c[mt][nt][0] + c[mt][nt][1];
            psq [mt][0] += c[mt][nt][0]*c[mt][nt][0] + c[mt][nt][1]*c[mt][nt][1];
            psum[mt][1] += c[mt][nt][2] + c[mt][nt][3];
            psq [mt][1] += c[mt][nt][2]*c[mt][nt][2] + c[mt][nt][3]*c[mt][nt][3];
        }
    #pragma unroll
    for (int mt = 0; mt < 2; mt++)
        #pragma unroll
        for (int hi = 0; hi < 2; hi++) {
            float s = psum[mt][hi], q2 = psq[mt][hi];
            s  += __shfl_xor_sync(0xffffffffu, s, 1);  s  += __shfl_xor_sync(0xffffffffu, s, 2);
            q2 += __shfl_xor_sync(0xffffffffu, q2, 1); q2 += __shfl_xor_sync(0xffffffffu, q2, 2);
            if (tg == 0) {
                int r = wm * 32 + mt * 16 + g + 8 * hi;
                sPart[r * 8 + wn] = s;
                sPart[r * 8 + 4 + wn] = q2;
            }
        }
    __syncthreads();
    if (tid < TM) {
        float s  = sPart[tid*8+0] + sPart[tid*8+1] + sPart[tid*8+2] + sPart[tid*8+3];
        float q2 = sPart[tid*8+4] + sPart[tid*8+5] + sPart[tid*8+6] + sPart[tid*8+7];
        float mean = s * (1.0f / CH);
        float var  = q2 * (1.0f / CH) - mean * mean;
        sMean[tid] = mean;
        sRstd[tid] = rsqrtf(var + 1e-5f);
    }
    __syncthreads();

    // ---- normalize + relu; store bf16 OR fused linear+exp ----
    float pd[2][2] = {{0,0},{0,0}};
    #pragma unroll
    for (int mt = 0; mt < 2; mt++) {
        int r0 = wm * 32 + mt * 16 + g;
        float m0 = sMean[r0],   rs0 = sRstd[r0];
        float m1 = sMean[r0+8], rs1 = sRstd[r0+8];
        #pragma unroll
        for (int nt = 0; nt < 12; nt++) {
            int col0 = wn * 96 + nt * 8 + tg * 2;
            float ga0 = sGamma[col0], ga1 = sGamma[col0+1];
            float be0 = sBeta[col0],  be1 = sBeta[col0+1];
            float v0 = fmaxf(0.f, (c[mt][nt][0] - m0) * rs0 * ga0 + be0);
            float v1 = fmaxf(0.f, (c[mt][nt][1] - m0) * rs0 * ga1 + be1);
            float v2 = fmaxf(0.f, (c[mt][nt][2] - m1) * rs1 * ga0 + be0);
            float v3 = fmaxf(0.f, (c[mt][nt][3] - m1) * rs1 * ga1 + be1);
            if (!PRED) {
                size_t base0 = (rowBase + s0 + r0) * CH + col0;
                *(__nv_bfloat162*)(g_h1 + base0)          = __floats2bfloat162_rn(v0, v1);
                *(__nv_bfloat162*)(g_h1 + base0 + 8 * CH) = __floats2bfloat162_rn(v2, v3);
            } else {
                float w0 = sWl[col0], w1v = sWl[col0 + 1];
                pd[mt][0] += v0 * w0 + v1 * w1v;
                pd[mt][1] += v2 * w0 + v3 * w1v;
            }
        }
    }
    if (!PRED) {
        // publish h1 tile: order stores before flag (release)
        __syncthreads();
        __threadfence();
        if (tid == 0) *(volatile int*)&g_flag[bidx] = 1;
    } else {
        #pragma unroll
        for (int mt = 0; mt < 2; mt++)
            #pragma unroll
            for (int hi = 0; hi < 2; hi++) {
                float s = pd[mt][hi];
                s += __shfl_xor_sync(0xffffffffu, s, 1);
                s += __shfl_xor_sync(0xffffffffu, s, 2);
                if (tg == 0) {
                    int r = wm * 32 + mt * 16 + g + 8 * hi;
                    sPart[r * 8 + wn] = s;
                }
            }
        __syncthreads();
        if (tid < TM) {
            float s = sPart[tid*8+0] + sPart[tid*8+1] + sPart[tid*8+2] + sPart[tid*8+3];
            pred[rowBase + s0 + tid] = expf(s + bl[0]);
        }
    }
}

// ---------------- launch ----------------
extern "C" void kernel_launch(void* const* d_in, const int* in_sizes, int n_in,
                              void* d_out, int out_size) {
    const float* x     = (const float*)d_in[0];
    const int*   dur   = (const int*)  d_in[1];
    const float* w1    = (const float*)d_in[2];
    const float* b1    = (const float*)d_in[3];
    const float* g1    = (const float*)d_in[4];
    const float* beta1 = (const float*)d_in[5];
    const float* w2    = (const float*)d_in[6];
    const float* b2    = (const float*)d_in[7];
    const float* g2    = (const float*)d_in[8];
    const float* beta2 = (const float*)d_in[9];
    const float* wl    = (const float*)d_in[10];
    const float* bl    = (const float*)d_in[11];

    float* res  = (float*)d_out;
    float* pred = res + (size_t)BATCH * MAXOUT * CH;

    cudaFuncSetAttribute(conv_ln_kernel, cudaFuncAttributeMaxDynamicSharedMemorySize, SMEM_TOTAL);

    // prep: src table (cumsum+searchsorted) + bf16 conversions + flag reset
    prep_kernel<<<BATCH + (CVT_TOTAL + 255) / 256, 256>>>(x, w1, w2, dur);

    // fused: dual-layer pipelined conv + tail-filling gather blocks
    conv_ln_kernel<<<2 * NTILES + GBLK, NTHR, SMEM_TOTAL>>>(b1, g1, beta1, b2, g2, beta2,
                                                            wl, bl, x, res, pred);
}

// round 14
// speedup vs baseline: 1.3061x; 1.0682x over previous
#include <cuda_runtime.h>
#include <cuda_bf16.h>
#include <cstdint>
#include <math.h>

// ---------------- problem constants ----------------
#define BATCH   32
#define SEQ     1024
#define CH      384          // C == H == 384
#define KTOT    1152         // 3 * 384
#define MAXOUT  3072
#define ROWS    (BATCH*SEQ)  // 32768

// GEMM tiling (R9/R13 proven config)
#define TM      128
#define KC      32
#define NITER   (KTOT/KC)    // 36
#define APAD    40           // halves per A smem row -> 80B stride, LDSM conflict-free
#define BPAD    40
#define NTHR    512
#define NSTAGE  4
#define NTILES  256          // conv tiles per layer
#define TPB     8            // tiles per batch
#define GBLK    512          // fine-grained tail gather blocks
#define GROWS   192          // res rows per gather block (512*192 = 98304)

// smem layout (bytes)
#define A_BYTES (TM*APAD*2)                    // 10240
#define B_BYTES (CH*BPAD*2)                    // 30720
#define OFF_B     (NSTAGE*A_BYTES)             // 40960
#define OFF_PARAM (OFF_B + NSTAGE*B_BYTES)     // 163840
#define OFF_PART  (OFF_PARAM + 4*CH*4)         // 169984
#define OFF_MEAN  (OFF_PART + TM*8*4)          // 174080
#define OFF_RSTD  (OFF_MEAN + TM*4)            // 174592
#define SMEM_TOTAL (OFF_RSTD + TM*4)           // 175104

// ---------------- device scratch (no allocations allowed) ----------------
__device__ __nv_bfloat16 g_xbf[ROWS*CH];     // bf16 copy of x (filled by L1 conv CTAs)
__device__ __nv_bfloat16 g_h1 [ROWS*CH];     // layer-1 output (bf16)
__device__ __nv_bfloat16 g_w1T[CH*KTOT];     // w1 transposed: [o][k*CH+c]
__device__ __nv_bfloat16 g_w2T[CH*KTOT];
__device__ int           g_src[BATCH*MAXOUT]; // absolute x row per res row, or -1
__device__ int           g_flag[NTILES];     // layer-1 tile completion flags

// ---------------- prep kernel: weights + src table + flag reset (NO cvt_x) ----------------
#define WN     (CH*KTOT)
#define CVT_TOTAL (2*WN + NTILES)

__global__ void prep_kernel(const float* __restrict__ w1,
                            const float* __restrict__ w2,
                            const int*   __restrict__ dur) {
    if (blockIdx.x < BATCH) {
        __shared__ int cum[SEQ];
        __shared__ int part[256];
        const int b = blockIdx.x, t = threadIdx.x;
        int v0 = dur[b*SEQ + t*4], v1 = dur[b*SEQ + t*4+1];
        int v2 = dur[b*SEQ + t*4+2], v3 = dur[b*SEQ + t*4+3];
        part[t] = v0 + v1 + v2 + v3;
        __syncthreads();
        #pragma unroll
        for (int off = 1; off < 256; off <<= 1) {
            int a = (t >= off) ? part[t - off] : 0;
            __syncthreads();
            part[t] += a;
            __syncthreads();
        }
        int run = t ? part[t-1] : 0;
        run += v0; cum[t*4]   = run;
        run += v1; cum[t*4+1] = run;
        run += v2; cum[t*4+2] = run;
        run += v3; cum[t*4+3] = run;
        __syncthreads();
        const int total = cum[SEQ-1];
        for (int t2 = t; t2 < MAXOUT; t2 += 256) {
            int lo = 0, hi = SEQ;
            while (lo < hi) { int mid = (lo+hi)>>1; if (cum[mid] <= t2) lo = mid+1; else hi = mid; }
            g_src[b*MAXOUT + t2] = (t2 < total) ? (b*SEQ + min(lo, SEQ-1)) : -1;
        }
        return;
    }
    int i = (blockIdx.x - BATCH) * blockDim.x + threadIdx.x;
    if (i < 2*WN) {
        int j = i;
        const float* w = (j < WN) ? w1 : w2;
        __nv_bfloat16* dst = (j < WN) ? g_w1T : g_w2T;
        if (j >= WN) j -= WN;
        int o  = j / KTOT;
        int kc = j - o * KTOT;
        dst[(size_t)o * KTOT + kc] = __float2bfloat16(w[(size_t)kc * CH + o]);
    } else if (i < CVT_TOTAL) {
        g_flag[i - 2*WN] = 0;
    }
}

// ---------------- ptx helpers ----------------
__device__ __forceinline__ void mma16816(float* c, const uint32_t* a, uint32_t b0, uint32_t b1) {
    asm volatile(
        "mma.sync.aligned.m16n8k16.row.col.f32.bf16.bf16.f32 "
        "{%0,%1,%2,%3}, {%4,%5,%6,%7}, {%8,%9}, {%0,%1,%2,%3};\n"
        : "+f"(c[0]), "+f"(c[1]), "+f"(c[2]), "+f"(c[3])
        : "r"(a[0]), "r"(a[1]), "r"(a[2]), "r"(a[3]), "r"(b0), "r"(b1));
}
__device__ __forceinline__ void ldsm4(uint32_t* r, uint32_t addr) {
    asm volatile("ldmatrix.sync.aligned.m8n8.x4.shared.b16 {%0,%1,%2,%3}, [%4];\n"
                 : "=r"(r[0]), "=r"(r[1]), "=r"(r[2]), "=r"(r[3]) : "r"(addr));
}
__device__ __forceinline__ void cp_async16(uint32_t dst, const void* gptr, int sz) {
    asm volatile("cp.async.cg.shared.global [%0], [%1], 16, %2;\n" :: "r"(dst), "l"(gptr), "r"(sz));
}
__device__ __forceinline__ void cp_async16(uint32_t dst, const void* gptr) {
    asm volatile("cp.async.cg.shared.global [%0], [%1], 16;\n" :: "r"(dst), "l"(gptr));
}
__device__ __forceinline__ void cp_commit() { asm volatile("cp.async.commit_group;\n"); }
__device__ __forceinline__ void cp_wait2()  { asm volatile("cp.async.wait_group 2;\n"); }
__device__ __forceinline__ void cp_wait1()  { asm volatile("cp.async.wait_group 1;\n"); }
__device__ __forceinline__ void cp_wait0()  { asm volatile("cp.async.wait_group 0;\n"); }

// ---------------- fused kernel ----------------
// Blocks 0..255:    L1 conv tiles: self-convert own x rows -> bf16, GEMM -> g_h1 + flag
// Blocks 256..511:  L2 conv tiles (spin on <=3 neighbor flags) -> pred
// Blocks 512..1023: fine-grained res gather (dispatched last -> fill conv tail wave)
__global__ __launch_bounds__(NTHR, 1)
void conv_ln_kernel(const float* __restrict__ b1v,
                    const float* __restrict__ g1v,
                    const float* __restrict__ be1v,
                    const float* __restrict__ b2v,
                    const float* __restrict__ g2v,
                    const float* __restrict__ be2v,
                    const float* __restrict__ wl,
                    const float* __restrict__ bl,
                    const float* __restrict__ x,
                    float* __restrict__ res,
                    float* __restrict__ pred)
{
    const int tid = threadIdx.x;

    // ---- tail gather blocks: warp-per-row copy via g_src ----
    if (blockIdx.x >= 2 * NTILES) {
        const int gb = blockIdx.x - 2 * NTILES;       // 0..GBLK-1
        const int wrp = tid >> 5, lane = tid & 31;    // 16 warps, 12 rows each
        const float4* xf4   = (const float4*)x;
        float4*       resf4 = (float4*)res;
        const float4  z = make_float4(0.f, 0.f, 0.f, 0.f);
        const int rbase = gb * GROWS;
        for (int rr = wrp; rr < GROWS; rr += 16) {
            int row = rbase + rr;
            int srow = g_src[row];
            float4* op = resf4 + (size_t)row * 96;
            if (srow < 0) {
                op[lane] = z; op[lane + 32] = z; op[lane + 64] = z;
            } else {
                const float4* xp = xf4 + (size_t)srow * 96;
                op[lane]      = xp[lane];
                op[lane + 32] = xp[lane + 32];
                op[lane + 64] = xp[lane + 64];
            }
        }
        return;
    }

    extern __shared__ char smem[];
    const uint32_t smem_base = (uint32_t)__cvta_generic_to_shared(smem);
    float* sBias  = (float*)(smem + OFF_PARAM);
    float* sGamma = sBias  + CH;
    float* sBeta  = sGamma + CH;
    float* sWl    = sBeta  + CH;
    float* sPart  = (float*)(smem + OFF_PART);   // [TM][8]
    float* sMean  = (float*)(smem + OFF_MEAN);   // [TM]
    float* sRstd  = (float*)(smem + OFF_RSTD);   // [TM]

    const bool PRED = blockIdx.x >= NTILES;
    const int  bidx = PRED ? (blockIdx.x - NTILES) : blockIdx.x;   // tile 0..255

    const __nv_bfloat16* Ain = PRED ? g_h1  : g_xbf;
    const __nv_bfloat16* WT  = PRED ? g_w2T : g_w1T;
    const float* bias  = PRED ? b2v  : b1v;
    const float* gamma = PRED ? g2v  : g1v;
    const float* beta  = PRED ? be2v : be1v;

    const int b    = bidx >> 3;             // 8 tiles per batch (1024/128)
    const int s0   = (bidx & (TPB - 1)) * TM;
    const size_t rowBase = (size_t)b * SEQ;

    if (tid < CH) {
        sBias[tid]  = bias[tid];
        sGamma[tid] = gamma[tid];
        sBeta[tid]  = beta[tid];
        sWl[tid]    = PRED ? wl[tid] : 0.0f;
    }

    if (!PRED) {
        // ---- self-convert the x rows this CTA's A-loader will read ----
        const int lo = max(s0 - 1, 0);
        const int hi = min(s0 + TM + 1, SEQ);
        const int n2 = (hi - lo) * (CH / 2);        // float2 elements
        const float2* xs = (const float2*)(x + (rowBase + lo) * CH);
        __nv_bfloat162* xd = (__nv_bfloat162*)(g_xbf + (rowBase + lo) * CH);
        for (int i = tid; i < n2; i += NTHR) {
            float2 v = xs[i];
            xd[i] = __floats2bfloat162_rn(v.x, v.y);
        }
        __threadfence();
        __syncthreads();
    } else {
        // ---- wait for the layer-1 tiles whose rows we read ----
        if (tid == 0) {
            int i = bidx & (TPB - 1), base = bidx & ~(TPB - 1);
            int lo = base + max(i - 1, 0), hi = base + min(i + 1, TPB - 1);
            for (int d = lo; d <= hi; d++)
                while (*(volatile int*)&g_flag[d] == 0) {}
        }
        __threadfence();
        __syncthreads();
    }

    // ---- tile loader (cp.async, padded layout) ----
    auto load_tile = [&](int ci, int st) {
        const int k  = ci / 12;             // conv tap 0..2
        const int c0 = (ci % 12) * KC;      // channel base within tap
        const uint32_t Ad = smem_base + st * A_BYTES;
        const uint32_t Bd = smem_base + OFF_B + st * B_BYTES;
        {   // A: 128 rows x 64B = 512 x 16B reqs, 1 per thread
            int r = tid >> 2, seg = tid & 3;
            int gs = s0 + r + k - 1;                // batch-local padded row
            bool ok = (unsigned)gs < (unsigned)SEQ;
            const void* src = ok ? (const void*)(Ain + (rowBase + gs) * CH + c0 + seg * 8)
                                 : (const void*)Ain;
            cp_async16(Ad + (r * APAD + seg * 8) * 2, src, ok ? 16 : 0);
        }
        // B: 384 rows x 64B = 1536 reqs, 3 per thread
        #pragma unroll
        for (int e = 0; e < 3; e++) {
            int j = tid + e * NTHR;
            int n = j >> 2, seg = j & 3;
            cp_async16(Bd + (n * BPAD + seg * 8) * 2,
                       WT + (size_t)n * KTOT + ci * KC + seg * 8);
        }
    };

    const int wid = tid >> 5, lane = tid & 31;
    const int wm = wid >> 2, wn = wid & 3;   // 4x4 warp grid; warp tile 32(M) x 96(N)

    const int aRow = wm * 32 + (lane & 7) + ((lane >> 3) & 1) * 8;
    const int aCol = (lane >> 4) * 8;                    // halves
    const uint32_t aBase = (uint32_t)((aRow * APAD + aCol) * 2);
    const int bRow = wn * 96 + (lane & 7) + ((lane >> 4) & 1) * 8;
    const int bCol = ((lane >> 3) & 1) * 8;              // halves
    const uint32_t bBase = (uint32_t)((bRow * BPAD + bCol) * 2);

    float c[2][12][4];
    #pragma unroll
    for (int mt = 0; mt < 2; mt++)
        #pragma unroll
        for (int nt = 0; nt < 12; nt++)
            #pragma unroll
            for (int i = 0; i < 4; i++) c[mt][nt][i] = 0.0f;

    load_tile(0, 0); cp_commit();
    load_tile(1, 1); cp_commit();

    for (int ci = 0; ci < NITER; ci++) {
        const int st = ci & 3;
        if (ci + 2 < NITER) { load_tile(ci + 2, (ci + 2) & 3); cp_commit(); cp_wait2(); }
        else if (ci == NITER - 2) cp_wait1();
        else cp_wait0();
        __syncthreads();

        const uint32_t Asb = smem_base + st * A_BYTES + aBase;
        const uint32_t Bsb = smem_base + OFF_B + st * B_BYTES + bBase;
        #pragma unroll
        for (int ks = 0; ks < 2; ks++) {
            uint32_t a[2][4];
            ldsm4(a[0], Asb + ks * 32);                       // rows wm*32 +  0..15
            ldsm4(a[1], Asb + 16 * APAD * 2 + ks * 32);       // rows wm*32 + 16..31
            #pragma unroll
            for (int np = 0; np < 6; np++) {
                uint32_t bb[4];                               // 2 n8 fragments
                ldsm4(bb, Bsb + np * 16 * BPAD * 2 + ks * 32);
                mma16816(c[0][2*np  ], a[0], bb[0], bb[1]);
                mma16816(c[1][2*np  ], a[1], bb[0], bb[1]);
                mma16816(c[0][2*np+1], a[0], bb[2], bb[3]);
                mma16816(c[1][2*np+1], a[1], bb[2], bb[3]);
            }
        }
    }
    __syncthreads();

    // ---- epilogue: +bias, LayerNorm stats ----
    const int g = lane >> 2, tg = lane & 3;
    float psum[2][2] = {{0,0},{0,0}}, psq[2][2] = {{0,0},{0,0}};
    #pragma unroll
    for (int mt = 0; mt < 2; mt++)
        #pragma unroll
        for (int nt = 0; nt < 12; nt++) {
            int col0 = wn * 96 + nt * 8 + tg * 2;
            float bb0 = sBias[col0], bb1 = sBias[col0 + 1];
            c[mt][nt][0] += bb0; c[mt][nt][1] += bb1;
            c[mt][nt][2] += bb0; c[mt][nt][3] += bb1;
            psum[mt][0] += c[mt][nt][0] + c[mt][nt][1];
            psq [mt][0] += c[mt][nt][0]*c[mt][nt][0] + c[mt][nt][1]*c[mt][nt][1];
            psum[mt][1] += c[mt][nt][2] + c[mt][nt][3];
            psq [mt][1] += c[mt][nt][2]*c[mt][nt][2] + c[mt][nt][3]*c[mt][nt][3];
        }
    #pragma unroll
    for (int mt = 0; mt < 2; mt++)
        #pragma unroll
        for (int hi = 0; hi < 2; hi++) {
            float s = psum[mt][hi], q2 = psq[mt][hi];
            s  += __shfl_xor_sync(0xffffffffu, s, 1);  s  += __shfl_xor_sync(0xffffffffu, s, 2);
            q2 += __shfl_xor_sync(0xffffffffu, q2, 1); q2 += __shfl_xor_sync(0xffffffffu, q2, 2);
            if (tg == 0) {
                int r = wm * 32 + mt * 16 + g + 8 * hi;
                sPart[r * 8 + wn] = s;
                sPart[r * 8 + 4 + wn] = q2;
            }
        }
    __syncthreads();
    if (tid < TM) {
        float s  = sPart[tid*8+0] + sPart[tid*8+1] + sPart[tid*8+2] + sPart[tid*8+3];
        float q2 = sPart[tid*8+4] + sPart[tid*8+5] + sPart[tid*8+6] + sPart[tid*8+7];
        float mean = s * (1.0f / CH);
        float var  = q2 * (1.0f / CH) - mean * mean;
        sMean[tid] = mean;
        sRstd[tid] = rsqrtf(var + 1e-5f);
    }
    __syncthreads();

    // ---- normalize + relu; store bf16 OR fused linear+exp ----
    float pd[2][2] = {{0,0},{0,0}};
    #pragma unroll
    for (int mt = 0; mt < 2; mt++) {
        int r0 = wm * 32 + mt * 16 + g;
        float m0 = sMean[r0],   rs0 = sRstd[r0];
        float m1 = sMean[r0+8], rs1 = sRstd[r0+8];
        #pragma unroll
        for (int nt = 0; nt < 12; nt++) {
            int col0 = wn * 96 + nt * 8 + tg * 2;
            float ga0 = sGamma[col0], ga1 = sGamma[col0+1];
            float be0 = sBeta[col0],  be1 = sBeta[col0+1];
            float v0 = fmaxf(0.f, (c[mt][nt][0] - m0) * rs0 * ga0 + be0);
            float v1 = fmaxf(0.f, (c[mt][nt][1] - m0) * rs0 * ga1 + be1);
            float v2 = fmaxf(0.f, (c[mt][nt][2] - m1) * rs1 * ga0 + be0);
            float v3 = fmaxf(0.f, (c[mt][nt][3] - m1) * rs1 * ga1 + be1);
            if (!PRED) {
                size_t base0 = (rowBase + s0 + r0) * CH + col0;
                *(__nv_bfloat162*)(g_h1 + base0)          = __floats2bfloat162_rn(v0, v1);
                *(__nv_bfloat162*)(g_h1 + base0 + 8 * CH) = __floats2bfloat162_rn(v2, v3);
            } else {
                float w0 = sWl[col0], w1v = sWl[col0 + 1];
                pd[mt][0] += v0 * w0 + v1 * w1v;
                pd[mt][1] += v2 * w0 + v3 * w1v;
            }
        }
    }
    if (!PRED) {
        // publish h1 tile: order stores before flag (release)
        __syncthreads();
        __threadfence();
        if (tid == 0) *(volatile int*)&g_flag[bidx] = 1;
    } else {
        #pragma unroll
        for (int mt = 0; mt < 2; mt++)
            #pragma unroll
            for (int hi = 0; hi < 2; hi++) {
                float s = pd[mt][hi];
                s += __shfl_xor_sync(0xffffffffu, s, 1);
                s += __shfl_xor_sync(0xffffffffu, s, 2);
                if (tg == 0) {
                    int r = wm * 32 + mt * 16 + g + 8 * hi;
                    sPart[r * 8 + wn] = s;
                }
            }
        __syncthreads();
        if (tid < TM) {
            float s = sPart[tid*8+0] + sPart[tid*8+1] + sPart[tid*8+2] + sPart[tid*8+3];
            pred[rowBase + s0 + tid] = expf(s + bl[0]);
        }
    }
}

// ---------------- launch ----------------
extern "C" void kernel_launch(void* const* d_in, const int* in_sizes, int n_in,
                              void* d_out, int out_size) {
    const float* x     = (const float*)d_in[0];
    const int*   dur   = (const int*)  d_in[1];
    const float* w1    = (const float*)d_in[2];
    const float* b1    = (const float*)d_in[3];
    const float* g1    = (const float*)d_in[4];
    const float* beta1 = (const float*)d_in[5];
    const float* w2    = (const float*)d_in[6];
    const float* b2    = (const float*)d_in[7];
    const float* g2    = (const float*)d_in[8];
    const float* beta2 = (const float*)d_in[9];
    const float* wl    = (const float*)d_in[10];
    const float* bl    = (const float*)d_in[11];

    float* res  = (float*)d_out;
    float* pred = res + (size_t)BATCH * MAXOUT * CH;

    cudaFuncSetAttribute(conv_ln_kernel, cudaFuncAttributeMaxDynamicSharedMemorySize, SMEM_TOTAL);

    // prep: weight transpose/convert + src table + flag reset (x converts in-kernel)
    prep_kernel<<<BATCH + (CVT_TOTAL + 255) / 256, 256>>>(w1, w2, dur);

    // fused: dual-layer pipelined conv + fine-grained tail-filling gather
    conv_ln_kernel<<<2 * NTILES + GBLK, NTHR, SMEM_TOTAL>>>(b1, g1, beta1, b2, g2, beta2,
                                                            wl, bl, x, res, pred);
}